// round 15
// baseline (speedup 1.0000x reference)
#include <cuda_runtime.h>
#include <cuda_bf16.h>
#include <cstdint>

#define N_TOTAL 16384
#define M_ROWS  4096
#define DIM     256
#define GRID    512
#define NTHR    512
#define CHUNK_ROWS   16
#define CHUNK_BYTES  (CHUNK_ROWS * DIM * 4)      // 16384 B
#define CHUNKS_TOTAL (N_TOTAL / CHUNK_ROWS)      // 1024
#define MASHUP_CHUNKS (M_ROWS / CHUNK_ROWS)      // 256
#define PAD     32            // 128B stride between atomic targets

// Scratch (no allocation; zero at module load; self-rezeroing across replays)
__device__ float g_s [DIM * PAD];   // column sums (padded); zeroed by final blk0
__device__ float g_vp[DIM * PAD];   // v (padded atomic accum); zeroed by colsum blk0
__device__ float g_c;               // scalar; zeroed by colsum blk0

// ---------------- minimal bulk-copy / mbarrier helpers ---------------------
__device__ __forceinline__ unsigned smem_u32(const void* p) {
    return (unsigned)__cvta_generic_to_shared(p);
}
__device__ __forceinline__ void mbar_init(unsigned bar, unsigned count) {
    asm volatile("mbarrier.init.shared.b64 [%0], %1;" :: "r"(bar), "r"(count) : "memory");
}
__device__ __forceinline__ void mbar_expect_tx(unsigned bar, unsigned bytes) {
    asm volatile("mbarrier.arrive.expect_tx.shared.b64 _, [%0], %1;"
                 :: "r"(bar), "r"(bytes) : "memory");
}
__device__ __forceinline__ void bulk_ld(unsigned dst, const void* src,
                                        unsigned bytes, unsigned bar) {
    asm volatile(
        "cp.async.bulk.shared::cluster.global.mbarrier::complete_tx::bytes "
        "[%0], [%1], %2, [%3];"
        :: "r"(dst), "l"(src), "r"(bytes), "r"(bar) : "memory");
}
__device__ __forceinline__ void mbar_wait(unsigned bar, unsigned parity) {
    unsigned done;
    do {
        asm volatile(
            "{\n\t.reg .pred p;\n\t"
            "mbarrier.try_wait.parity.acquire.cta.shared::cta.b64 p, [%1], %2, 0x989680;\n\t"
            "selp.b32 %0, 1, 0, p;\n\t}"
            : "=r"(done) : "r"(bar), "r"(parity) : "memory");
    } while (!done);
}

// ---------------------------------------------------------------------------
// k1: column sums of combine_new = [mashup ; new_api] via bulk-async loads.
// 512 blocks x 512 thr. Block b pulls chunks {b, b+512} (16 rows = 16KB each)
// into double-buffered SMEM with cp.async.bulk, accumulates from SMEM
// (conflict-free LDS.128), tree-reduces, RED.ADDs into padded g_s lines.
// Chunk c < 256 -> mashup rows, else new_api (chunks never straddle).
// ---------------------------------------------------------------------------
__global__ void __launch_bounds__(NTHR)
colsum_kernel(const float* __restrict__ mashup,
              const float* __restrict__ new_api) {
    __shared__ alignas(128) float4 buf[2][CHUNK_BYTES / 16];   // 2 x 16KB
    __shared__ alignas(8) uint64_t bars[2];
    __shared__ float4 sm4[NTHR];                                // 8KB tree

    const int t   = threadIdx.x;
    const int c4  = t & 63;
    const int sub = t >> 6;                  // 0..7
    const int bid = blockIdx.x;

    if (bid == 0) {                          // zero middle-stage accumulators
        #pragma unroll
        for (int m = 0; m < 16; ++m) g_vp[t + NTHR * m] = 0.f;
        if (t == 0) g_c = 0.f;
    }

    const unsigned bar0 = smem_u32(&bars[0]);
    const unsigned bar1 = smem_u32(&bars[1]);
    if (t == 0) { mbar_init(bar0, 1); mbar_init(bar1, 1); }
    __syncthreads();                         // init visible before any wait

    const int c0 = bid;                      // 0..511
    const int c1 = bid + GRID;               // 512..1023 (always new_api)
    const float* src0 = (c0 < MASHUP_CHUNKS)
        ? (mashup + (size_t)c0 * CHUNK_ROWS * DIM)
        : (new_api + (size_t)(c0 - MASHUP_CHUNKS) * CHUNK_ROWS * DIM);
    const float* src1 = new_api + (size_t)(c1 - MASHUP_CHUNKS) * CHUNK_ROWS * DIM;

    if (t == 0) {                            // same thread inited the barriers
        mbar_expect_tx(bar0, CHUNK_BYTES);
        bulk_ld(smem_u32(&buf[0][0]), src0, CHUNK_BYTES, bar0);
        mbar_expect_tx(bar1, CHUNK_BYTES);
        bulk_ld(smem_u32(&buf[1][0]), src1, CHUNK_BYTES, bar1);
    }

    float4 acc = make_float4(0.f, 0.f, 0.f, 0.f);
    #pragma unroll
    for (int s = 0; s < 2; ++s) {
        mbar_wait(s == 0 ? bar0 : bar1, 0);
        // 16 rows x 64 float4-cols; thread handles rows {sub, sub+8}, col c4
        const float4 a = buf[s][sub * 64 + c4];
        const float4 b = buf[s][(sub + 8) * 64 + c4];
        acc.x += a.x + b.x; acc.y += a.y + b.y;
        acc.z += a.z + b.z; acc.w += a.w + b.w;
    }

    sm4[t] = acc;
    __syncthreads();
    if (t < 64) {
        float4 r = sm4[t];
        #pragma unroll
        for (int s = 1; s < 8; ++s) {
            const float4 a = sm4[t + 64 * s];
            r.x += a.x; r.y += a.y; r.z += a.z; r.w += a.w;
        }
        atomicAdd(&g_s[(4 * t + 0) * PAD], r.x);
        atomicAdd(&g_s[(4 * t + 1) * PAD], r.y);
        atomicAdd(&g_s[(4 * t + 2) * PAD], r.z);
        atomicAdd(&g_s[(4 * t + 3) * PAD], r.w);
    }
}

// ---------------------------------------------------------------------------
// k2: middle stage (64 blocks x 256 thr), unchanged. Kernel boundary = sync.
// Block b: ksum cols jb..jb+3 = k_w^T s + N*k_b; scatter
// v += q_w[:,cols]*ksum_cols and c += q_b[cols].ksum_cols via padded atomics.
// ---------------------------------------------------------------------------
__global__ void __launch_bounds__(256, 4)
middle_kernel(const float* __restrict__ q_w,
              const float* __restrict__ q_b,
              const float* __restrict__ k_w,
              const float* __restrict__ k_b) {
    __shared__ float4 sm4[256];
    const int t  = threadIdx.x;
    const int jb = blockIdx.x * 4;

    const float  si = __ldcg(&g_s[t * PAD]);
    const float4 kw = *reinterpret_cast<const float4*>(
        k_w + (size_t)t * DIM + jb);
    sm4[t] = make_float4(si * kw.x, si * kw.y, si * kw.z, si * kw.w);
    __syncthreads();
    #pragma unroll
    for (int off = 128; off >= 1; off >>= 1) {
        if (t < off) {
            const float4 a = sm4[t], b = sm4[t + off];
            sm4[t] = make_float4(a.x + b.x, a.y + b.y, a.z + b.z, a.w + b.w);
        }
        __syncthreads();
    }
    if (t == 0) {
        const float4 kb = *reinterpret_cast<const float4*>(k_b + jb);
        float4 ks = sm4[0];
        ks.x += (float)N_TOTAL * kb.x;
        ks.y += (float)N_TOTAL * kb.y;
        ks.z += (float)N_TOTAL * kb.z;
        ks.w += (float)N_TOTAL * kb.w;
        sm4[0] = ks;
        const float4 qb = *reinterpret_cast<const float4*>(q_b + jb);
        atomicAdd(&g_c, qb.x * ks.x + qb.y * ks.y + qb.z * ks.z + qb.w * ks.w);
    }
    __syncthreads();
    const float4 ks = sm4[0];
    const float4 qw = *reinterpret_cast<const float4*>(
        q_w + (size_t)t * DIM + jb);
    atomicAdd(&g_vp[t * PAD],
              qw.x * ks.x + qw.y * ks.y + qw.z * ks.z + qw.w * ks.w);
}

// ---------------------------------------------------------------------------
// k3: out[i] = (combine[i].v + c)/16, combine = [mashup ; api], bulk loads.
// Same chunking as k1 (chunk c < 256 -> mashup, else api). Per chunk: 16
// warps x 1 row; lane reads 2 float4 from SMEM, dot with v, shuffle-reduce.
// Block 0 zeroes g_s for the next graph replay (never read here).
// ---------------------------------------------------------------------------
__global__ void __launch_bounds__(NTHR)
final_kernel(const float* __restrict__ mashup,
             const float* __restrict__ api,
             float* __restrict__ out) {
    __shared__ alignas(128) float4 buf[2][CHUNK_BYTES / 16];   // 2 x 16KB
    __shared__ alignas(8) uint64_t bars[2];
    __shared__ float vs[DIM];
    __shared__ float sc;

    const int t   = threadIdx.x;
    const int bid = blockIdx.x;

    if (bid == 0) {                          // reset g_s for next replay
        #pragma unroll
        for (int m = 0; m < 16; ++m) g_s[t + NTHR * m] = 0.f;
    }

    const unsigned bar0 = smem_u32(&bars[0]);
    const unsigned bar1 = smem_u32(&bars[1]);
    if (t == 0) { mbar_init(bar0, 1); mbar_init(bar1, 1); }
    if (t < DIM) vs[t] = __ldcg(&g_vp[t * PAD]);
    if (t == 0)  sc    = __ldcg(&g_c);
    __syncthreads();                         // init + vs/sc visible

    const int c0 = bid;
    const int c1 = bid + GRID;               // always api
    const float* src0 = (c0 < MASHUP_CHUNKS)
        ? (mashup + (size_t)c0 * CHUNK_ROWS * DIM)
        : (api + (size_t)(c0 - MASHUP_CHUNKS) * CHUNK_ROWS * DIM);
    const float* src1 = api + (size_t)(c1 - MASHUP_CHUNKS) * CHUNK_ROWS * DIM;

    if (t == 0) {
        mbar_expect_tx(bar0, CHUNK_BYTES);
        bulk_ld(smem_u32(&buf[0][0]), src0, CHUNK_BYTES, bar0);
        mbar_expect_tx(bar1, CHUNK_BYTES);
        bulk_ld(smem_u32(&buf[1][0]), src1, CHUNK_BYTES, bar1);
    }

    const int warp = t >> 5, lane = t & 31;
    const float4* vp = reinterpret_cast<const float4*>(vs);
    const float4 v0 = vp[lane], v1 = vp[lane + 32];
    const float scale = 0.0625f;             // 1/sqrt(256)

    #pragma unroll
    for (int s = 0; s < 2; ++s) {
        mbar_wait(s == 0 ? bar0 : bar1, 0);
        // warp w handles row w of the chunk
        const float4 x0 = buf[s][warp * 64 + lane];
        const float4 x1 = buf[s][warp * 64 + lane + 32];
        float a = x0.x * v0.x + x0.y * v0.y + x0.z * v0.z + x0.w * v0.w
                + x1.x * v1.x + x1.y * v1.y + x1.z * v1.z + x1.w * v1.w;
        #pragma unroll
        for (int off = 16; off > 0; off >>= 1)
            a += __shfl_xor_sync(0xFFFFFFFFu, a, off);
        if (lane == 0) {
            const int chunk = (s == 0) ? c0 : c1;
            out[chunk * CHUNK_ROWS + warp] = (a + sc) * scale;
        }
    }
}

// ---------------------------------------------------------------------------
// Launch. Inputs (metadata order): mashup, api, new_api, q_w, q_b, k_w, k_b,
// embedding_dim (fixed 256, unused). THREE launches; only local mbarrier
// waits for this CTA's own bulk copies — no cross-CTA sync, no global spins.
// ---------------------------------------------------------------------------
extern "C" void kernel_launch(void* const* d_in, const int* in_sizes, int n_in,
                              void* d_out, int out_size) {
    const float* mashup  = (const float*)d_in[0];
    const float* api     = (const float*)d_in[1];
    const float* new_api = (const float*)d_in[2];
    const float* q_w     = (const float*)d_in[3];
    const float* q_b     = (const float*)d_in[4];
    const float* k_w     = (const float*)d_in[5];
    const float* k_b     = (const float*)d_in[6];
    float* out = (float*)d_out;

    colsum_kernel<<<GRID, NTHR>>>(mashup, new_api);
    middle_kernel<<<DIM / 4, 256>>>(q_w, q_b, k_w, k_b);
    final_kernel <<<GRID, NTHR>>>(mashup, api, out);
}

// round 17
// speedup vs baseline: 1.0067x; 1.0067x over previous
#include <cuda_runtime.h>
#include <cuda_bf16.h>
#include <cstdint>

#define N_TOTAL 16384
#define M_ROWS  4096
#define DIM     256
#define GRID    296          // exactly 2 blocks per SM (148 x 2)
#define NTHR    512
#define NTHREADS (GRID * NTHR)          // 151552
#define TOTAL_F4 (N_TOTAL * (DIM / 4))  // 1048576 float4s in combined matrix
#define SEG_F4   (M_ROWS * (DIM / 4))   // 262144 float4s in mashup
#define PAD     32           // 128B stride between atomic targets

// Scratch (no allocation; zero at module load; self-rezeroing across replays)
__device__ float g_s [DIM * PAD];   // column sums (padded); zeroed by final blk0
__device__ float g_vp[DIM * PAD];   // v (padded atomic accum); zeroed by colsum blk0
__device__ float g_c;               // scalar; zeroed by colsum blk0

// L2 persistence via access policy (the form ptxas accepts for v4.f32):
// createpolicy.fractional.L2::evict_last + ld.global.nc.L2::cache_hint.
__device__ __forceinline__ uint64_t mk_persist_policy() {
    uint64_t p;
    asm("createpolicy.fractional.L2::evict_last.b64 %0, 1.0;" : "=l"(p));
    return p;
}
__device__ __forceinline__ float4 ldg_persist(const float4* p, uint64_t pol) {
    float4 v;
    asm volatile("ld.global.nc.L2::cache_hint.v4.f32 {%0,%1,%2,%3}, [%4], %5;"
                 : "=f"(v.x), "=f"(v.y), "=f"(v.z), "=f"(v.w)
                 : "l"(p), "l"(pol));
    return v;
}

// ---------------------------------------------------------------------------
// k1: column sums of combine_new = [mashup ; new_api], linear addressing
// (R13 shape, measured 7.17us). 296 x 512 @ 2 blocks/SM, 64-reg budget,
// 7 independent float4 loads/thread, each with the evict_last policy.
// Thread g = bid*512+t reads p = g + k*151552, k=0..6 (k=6 predicated).
// 151552 % 64 == 0 => column c4 = g&63 constant per thread.
// ---------------------------------------------------------------------------
__global__ void __launch_bounds__(NTHR, 2)
colsum_kernel(const float* __restrict__ mashup,
              const float* __restrict__ new_api) {
    const int t   = threadIdx.x;
    const int bid = blockIdx.x;
    const int g   = bid * NTHR + t;
    const uint64_t pol = mk_persist_policy();

    if (bid == 0) {                          // zero middle-stage accumulators
        #pragma unroll
        for (int m = 0; m < 16; ++m) g_vp[t + NTHR * m] = 0.f;
        if (t == 0) g_c = 0.f;
    }

    float4 acc = make_float4(0.f, 0.f, 0.f, 0.f);
    #pragma unroll
    for (int k = 0; k < 7; ++k) {
        const int p = g + k * NTHREADS;
        if (k < 6 || p < TOTAL_F4) {         // only k=6 needs the bound
            const float4* base = (p < SEG_F4)
                ? (reinterpret_cast<const float4*>(mashup) + p)
                : (reinterpret_cast<const float4*>(new_api) + (p - SEG_F4));
            const float4 x = ldg_persist(base, pol);
            acc.x += x.x; acc.y += x.y; acc.z += x.z; acc.w += x.w;
        }
    }

    // block tree-reduce over the 8 sub-groups sharing each c4
    __shared__ float4 sm4[NTHR];
    sm4[t] = acc;
    __syncthreads();
    if (t < 64) {
        float4 r = sm4[t];
        #pragma unroll
        for (int s = 1; s < 8; ++s) {
            const float4 a = sm4[t + 64 * s];
            r.x += a.x; r.y += a.y; r.z += a.z; r.w += a.w;
        }
        atomicAdd(&g_s[(4 * t + 0) * PAD], r.x);
        atomicAdd(&g_s[(4 * t + 1) * PAD], r.y);
        atomicAdd(&g_s[(4 * t + 2) * PAD], r.z);
        atomicAdd(&g_s[(4 * t + 3) * PAD], r.w);
    }
}

// ---------------------------------------------------------------------------
// k2: middle stage (64 blocks x 256 thr). Kernel boundary = sync.
// Block b: ksum cols jb..jb+3 = k_w^T s + N*k_b; scatter
// v += q_w[:,cols]*ksum_cols and c += q_b[cols].ksum_cols via padded atomics.
// ---------------------------------------------------------------------------
__global__ void __launch_bounds__(256, 4)
middle_kernel(const float* __restrict__ q_w,
              const float* __restrict__ q_b,
              const float* __restrict__ k_w,
              const float* __restrict__ k_b) {
    __shared__ float4 sm4[256];
    const int t  = threadIdx.x;
    const int jb = blockIdx.x * 4;

    const float  si = __ldcg(&g_s[t * PAD]);
    const float4 kw = *reinterpret_cast<const float4*>(
        k_w + (size_t)t * DIM + jb);
    sm4[t] = make_float4(si * kw.x, si * kw.y, si * kw.z, si * kw.w);
    __syncthreads();
    #pragma unroll
    for (int off = 128; off >= 1; off >>= 1) {
        if (t < off) {
            const float4 a = sm4[t], b = sm4[t + off];
            sm4[t] = make_float4(a.x + b.x, a.y + b.y, a.z + b.z, a.w + b.w);
        }
        __syncthreads();
    }
    if (t == 0) {
        const float4 kb = *reinterpret_cast<const float4*>(k_b + jb);
        float4 ks = sm4[0];
        ks.x += (float)N_TOTAL * kb.x;
        ks.y += (float)N_TOTAL * kb.y;
        ks.z += (float)N_TOTAL * kb.z;
        ks.w += (float)N_TOTAL * kb.w;
        sm4[0] = ks;
        const float4 qb = *reinterpret_cast<const float4*>(q_b + jb);
        atomicAdd(&g_c, qb.x * ks.x + qb.y * ks.y + qb.z * ks.z + qb.w * ks.w);
    }
    __syncthreads();
    const float4 ks = sm4[0];
    const float4 qw = *reinterpret_cast<const float4*>(
        q_w + (size_t)t * DIM + jb);
    atomicAdd(&g_vp[t * PAD],
              qw.x * ks.x + qw.y * ks.y + qw.z * ks.z + qw.w * ks.w);
}

// ---------------------------------------------------------------------------
// k3: out[i] = (combine[i].v + c)/16, combine = [mashup ; api] (R13 shape).
// 296 x 512 @ 2 blocks/SM. Warp w owns rows 4w..4w+3 (warp-uniform guard;
// 4096 % 4 == 0 so no mashup/api straddle). 8 independent policy-tagged
// loads per thread. Block 0 zeroes g_s for the next graph replay.
// ---------------------------------------------------------------------------
__global__ void __launch_bounds__(NTHR, 2)
final_kernel(const float* __restrict__ mashup,
             const float* __restrict__ api,
             float* __restrict__ out) {
    __shared__ float vs[DIM];
    __shared__ float sc;
    const int t = threadIdx.x;
    const uint64_t pol = mk_persist_policy();

    if (blockIdx.x == 0) {                   // reset g_s for next replay
        #pragma unroll
        for (int m = 0; m < 16; ++m) g_s[t + NTHR * m] = 0.f;
    }

    if (t < DIM) vs[t] = __ldcg(&g_vp[t * PAD]);
    if (t == 0)  sc    = __ldcg(&g_c);
    __syncthreads();

    const int warp = t >> 5, lane = t & 31;
    const int row0 = (blockIdx.x * 16 + warp) * 4;   // 4 rows per warp
    if (row0 >= N_TOTAL) return;                      // warp-uniform

    const float* src;
    int base;
    if (row0 < M_ROWS) { src = mashup; base = row0; }
    else               { src = api;    base = row0 - M_ROWS; }

    const float4* vp = reinterpret_cast<const float4*>(vs);
    const float4 v0 = vp[lane], v1 = vp[lane + 32];

    float4 x0[4], x1[4];
    #pragma unroll
    for (int r = 0; r < 4; ++r) {
        const float4* p = reinterpret_cast<const float4*>(
            src + (size_t)(base + r) * DIM);
        x0[r] = ldg_persist(p + lane, pol);
        x1[r] = ldg_persist(p + lane + 32, pol);
    }

    float acc[4];
    #pragma unroll
    for (int r = 0; r < 4; ++r) {
        acc[r] = x0[r].x * v0.x + x0[r].y * v0.y + x0[r].z * v0.z + x0[r].w * v0.w
               + x1[r].x * v1.x + x1[r].y * v1.y + x1[r].z * v1.z + x1[r].w * v1.w;
    }
    #pragma unroll
    for (int r = 0; r < 4; ++r) {
        float a = acc[r];
        #pragma unroll
        for (int off = 16; off > 0; off >>= 1)
            a += __shfl_xor_sync(0xFFFFFFFFu, a, off);
        if (lane == 0)
            out[row0 + r] = (a + sc) * 0.0625f;      // 1/sqrt(256)
    }
}

// ---------------------------------------------------------------------------
// Launch. Inputs (metadata order): mashup, api, new_api, q_w, q_b, k_w, k_b,
// embedding_dim (fixed 256, unused). THREE launches, zero device-side spins.
// ---------------------------------------------------------------------------
extern "C" void kernel_launch(void* const* d_in, const int* in_sizes, int n_in,
                              void* d_out, int out_size) {
    const float* mashup  = (const float*)d_in[0];
    const float* api     = (const float*)d_in[1];
    const float* new_api = (const float*)d_in[2];
    const float* q_w     = (const float*)d_in[3];
    const float* q_b     = (const float*)d_in[4];
    const float* k_w     = (const float*)d_in[5];
    const float* k_b     = (const float*)d_in[6];
    float* out = (float*)d_out;

    colsum_kernel<<<GRID, NTHR>>>(mashup, new_api);
    middle_kernel<<<DIM / 4, 256>>>(q_w, q_b, k_w, k_b);
    final_kernel <<<GRID, NTHR>>>(mashup, api, out);
}